// round 8
// baseline (speedup 1.0000x reference)
#include <cuda_runtime.h>
#include <cuda_fp16.h>
#include <math.h>
#include <stdint.h>

// Problem constants
#define NB   4
#define CC   128
#define HH   128
#define WW   256
#define HWSZ (HH * WW)          // 32768
#define NHW  (NB * HWSZ)        // 131072
#define DIM  128
#define NWP  4
#define APIT 136                // A smem pitch (words); %32==8 -> conflict-free frags
#define BPIT 264                // fused K|V B-panel pitch; %32==8
#define MT   4                  // m-tiles per CTA
#define NCH  (MT * 4)           // 16 chunks per CTA
#define A_STG_W (32 * APIT)     // words per A stage = 4352
#define KV_BIAS_BLOCKS 8

// Device-global scratch: K/V/Q fp16 (fp32 math)
__device__ __half g_K[(size_t)NHW * DIM];
__device__ __half g_V[(size_t)NHW * DIM];
__device__ __half g_Q[(size_t)NHW * DIM];
__device__ float  g_kb[NWP * DIM];
__device__ float  g_vb[NWP * DIM];

__device__ __forceinline__ float inv_dt(int t2) {
    return exp2f(-(float)t2 * (13.287712379549449f / 32.0f));
}

__device__ __forceinline__ void cp16(uint32_t saddr, const void* g) {
    asm volatile("cp.async.cg.shared.global [%0], [%1], 16;" :: "r"(saddr), "l"(g));
}
__device__ __forceinline__ void cp_commit() {
    asm volatile("cp.async.commit_group;" ::: "memory");
}
template<int N> __device__ __forceinline__ void cp_wait() {
    asm volatile("cp.async.wait_group %0;" :: "n"(N) : "memory");
}

__device__ __forceinline__ void mma_tf32(float d[4], const uint32_t a[4],
                                         uint32_t b0, uint32_t b1) {
    asm volatile(
        "mma.sync.aligned.m16n8k8.row.col.f32.tf32.tf32.f32 "
        "{%0,%1,%2,%3}, {%4,%5,%6,%7}, {%8,%9}, {%0,%1,%2,%3};\n"
        : "+f"(d[0]), "+f"(d[1]), "+f"(d[2]), "+f"(d[3])
        : "r"(a[0]), "r"(a[1]), "r"(a[2]), "r"(a[3]), "r"(b0), "r"(b1));
}

// ---------------------------------------------------------------------------
// Bias path (runs as blocks 0..7 of the kv launch): window position-bias
// projections g_kb/g_vb; consumed only by attn_kernel (launches later).
// ---------------------------------------------------------------------------
__device__ void bias_path(int bid, int t,
                          const float* __restrict__ kw, const float* __restrict__ kb,
                          const float* __restrict__ vw, const float* __restrict__ vb) {
    __shared__ float pb[DIM];
    int w      = bid & 3;
    int matrix = bid >> 2;
    if (t < DIM) {
        int oy = w >> 1, ox = w & 1;
        float coord = (t < 64) ? (float)oy : (float)ox;
        int ii = t & 63;
        int t2 = ii >> 1;
        float arg = coord * (6.283185307179586f / 1.000001f) * inv_dt(t2);
        float s, c;
        sincosf(arg, &s, &c);
        pb[t] = (ii & 1) ? c : s;
    }
    __syncthreads();

    const float* W  = matrix ? vw : kw;
    const float* Bb = matrix ? vb : kb;
    float* dst      = matrix ? g_vb : g_kb;

    int d = t >> 2, q = t & 3;
    float acc = 0.f;
    int cbase = q * 32;
#pragma unroll 8
    for (int c = 0; c < 32; ++c)
        acc += pb[cbase + c] * W[(cbase + c) * DIM + d];
    acc += __shfl_xor_sync(0xffffffffu, acc, 1);
    acc += __shfl_xor_sync(0xffffffffu, acc, 2);
    if (q == 0)
        dst[w * DIM + d] = acc + Bb[d];
}

// ---------------------------------------------------------------------------
// Kernel 1: K/V GEMM (+ bias blocks). B panel ([kw|vw], fp32) resident.
// 4 m-tiles per CTA, 16-chunk A stream, 4-stage ring, lookahead 3.
// ---------------------------------------------------------------------------
__device__ __forceinline__ void kv_fillA(uint32_t sm_u, const float* __restrict__ feat,
                                         int n, int pix0_blk, int gc, int t) {
    int stage = gc & 3;
    int tile  = gc >> 2;
    int kb    = (gc & 3) * 32;
    int pix0  = pix0_blk + tile * 128;
    uint32_t As_u = sm_u + (uint32_t)(stage * A_STG_W) * 4u;
#pragma unroll
    for (int j = 0; j < 2; ++j) {
        int li = j * 512 + t;
        int r = li >> 5, m4 = li & 31;
        cp16(As_u + (r * APIT + m4 * 4) * 4,
             feat + (size_t)(n * CC + kb + r) * HWSZ + pix0 + m4 * 4);
    }
}

__device__ __forceinline__ void mma_chunk_kv(const float* __restrict__ As,
                                             const float* __restrict__ Bs,
                                             float acc[2][8][4],
                                             int m0w, int n0w, int q, int g) {
#pragma unroll
    for (int ks = 0; ks < 4; ++ks) {
        int k0 = ks * 8;
        uint32_t a[2][4];
#pragma unroll
        for (int mi = 0; mi < 2; ++mi) {
            int m = m0w + mi * 16 + g;
            a[mi][0] = __float_as_uint(As[(k0 + q) * APIT + m]);
            a[mi][1] = __float_as_uint(As[(k0 + q) * APIT + m + 8]);
            a[mi][2] = __float_as_uint(As[(k0 + q + 4) * APIT + m]);
            a[mi][3] = __float_as_uint(As[(k0 + q + 4) * APIT + m + 8]);
        }
#pragma unroll
        for (int nj = 0; nj < 8; ++nj) {
            int nn = n0w + nj * 8 + g;
            uint32_t b0 = __float_as_uint(Bs[(k0 + q) * BPIT + nn]);
            uint32_t b1 = __float_as_uint(Bs[(k0 + q + 4) * BPIT + nn]);
#pragma unroll
            for (int mi = 0; mi < 2; ++mi)
                mma_tf32(acc[mi][nj], a[mi], b0, b1);
        }
    }
}

__global__ __launch_bounds__(512, 1)
void gemm_kv_kernel(const float* __restrict__ feat,
                    const float* __restrict__ kw,
                    const float* __restrict__ vw,
                    const float* __restrict__ kb_,
                    const float* __restrict__ vb_) {
    int t = threadIdx.x;
    if (blockIdx.x < KV_BIAS_BLOCKS) {
        bias_path(blockIdx.x, t, kw, kb_, vw, vb_);
        return;
    }
    int bid = blockIdx.x - KV_BIAS_BLOCKS;

    extern __shared__ float sm[];
    float* Bs = sm + 4 * A_STG_W;                      // resident B panel
    uint32_t sm_u = (uint32_t)__cvta_generic_to_shared(sm);
    uint32_t Bs_u = sm_u + (uint32_t)(4 * A_STG_W) * 4u;
    int m0_blk = bid * (128 * MT);
    int n      = m0_blk / HWSZ;
    int pix0_blk = m0_blk % HWSZ;

    // Group 0: B panel + A chunk 0
#pragma unroll
    for (int j = 0; j < 16; ++j) {
        int li = j * 512 + t;
        int r = li >> 6, d4 = li & 63;
        const float* src = (d4 < 32) ? (kw + r * DIM + d4 * 4)
                                     : (vw + r * DIM + (d4 - 32) * 4);
        int col = (d4 < 32) ? (d4 * 4) : (128 + (d4 - 32) * 4);
        cp16(Bs_u + (r * BPIT + col) * 4, src);
    }
    kv_fillA(sm_u, feat, n, pix0_blk, 0, t);
    cp_commit();
    kv_fillA(sm_u, feat, n, pix0_blk, 1, t); cp_commit();
    kv_fillA(sm_u, feat, n, pix0_blk, 2, t); cp_commit();

    int w = t >> 5, lane = t & 31;
    int m0w = (w & 3) * 32, n0w = (w >> 2) * 64;
    int q = lane & 3, g = lane >> 2;

    float acc[2][8][4];
#pragma unroll
    for (int mi = 0; mi < 2; ++mi)
#pragma unroll
        for (int nj = 0; nj < 8; ++nj)
#pragma unroll
            for (int e = 0; e < 4; ++e) acc[mi][nj][e] = 0.f;

#pragma unroll 1
    for (int gc = 0; gc < NCH; ++gc) {
        if (gc <= NCH - 3)      cp_wait<2>();
        else if (gc == NCH - 2) cp_wait<1>();
        else                    cp_wait<0>();
        __syncthreads();
        if (gc + 3 < NCH) { kv_fillA(sm_u, feat, n, pix0_blk, gc + 3, t); cp_commit(); }

        const float* As = sm + (gc & 3) * A_STG_W;
        const float* Bk = Bs + ((gc & 3) * 32) * BPIT;   // chunk's channel rows
        mma_chunk_kv(As, Bk, acc, m0w, n0w, q, g);

        if ((gc & 3) == 3) {
            int m0 = m0_blk + (gc >> 2) * 128;
#pragma unroll
            for (int mi = 0; mi < 2; ++mi) {
#pragma unroll
                for (int nj = 0; nj < 8; ++nj) {
                    int r0 = m0 + m0w + mi * 16 + g;
                    int col = n0w + nj * 8 + q * 2;
                    __half* dst = (col < 128) ? (g_K + (size_t)r0 * DIM + col)
                                              : (g_V + (size_t)r0 * DIM + (col - 128));
                    *(__half2*)dst = __floats2half2_rn(acc[mi][nj][0], acc[mi][nj][1]);
                    *(__half2*)(dst + (size_t)8 * DIM) =
                        __floats2half2_rn(acc[mi][nj][2], acc[mi][nj][3]);
                    acc[mi][nj][0] = 0.f; acc[mi][nj][1] = 0.f;
                    acc[mi][nj][2] = 0.f; acc[mi][nj][3] = 0.f;
                }
            }
        }
    }
}

// ---------------------------------------------------------------------------
// Kernel 2: Q GEMM. q_w resident; 16-chunk ring; PE per chunk.
// ---------------------------------------------------------------------------
__device__ __forceinline__ void q_fillA(uint32_t sm_u, const float* __restrict__ feat,
                                        int n, int pix0_blk, int gc, int t) {
    int stage = gc & 3;
    int tile  = gc >> 2;
    int kb    = (gc & 3) * 32;
    int pix0  = pix0_blk + tile * 128;
    uint32_t As_u = sm_u + (uint32_t)(stage * A_STG_W) * 4u;
#pragma unroll
    for (int j = 0; j < 2; ++j) {
        int li = j * 512 + t;
        int r = li >> 5, m4 = li & 31;
        cp16(As_u + (r * APIT + m4 * 4) * 4,
             feat + (size_t)(n * CC + kb + r) * HWSZ + pix0 + m4 * 4);
    }
}

__device__ __forceinline__ void mma_chunk_q(const float* __restrict__ As,
                                            const float* __restrict__ Bs,   // chunk's rows
                                            float acc[2][4][4],
                                            int m0w, int n0w, int q, int g) {
#pragma unroll
    for (int ks = 0; ks < 4; ++ks) {
        int k0 = ks * 8;
        uint32_t a[2][4];
#pragma unroll
        for (int mi = 0; mi < 2; ++mi) {
            int m = m0w + mi * 16 + g;
            a[mi][0] = __float_as_uint(As[(k0 + q) * APIT + m]);
            a[mi][1] = __float_as_uint(As[(k0 + q) * APIT + m + 8]);
            a[mi][2] = __float_as_uint(As[(k0 + q + 4) * APIT + m]);
            a[mi][3] = __float_as_uint(As[(k0 + q + 4) * APIT + m + 8]);
        }
#pragma unroll
        for (int nj = 0; nj < 4; ++nj) {
            int nn = n0w + nj * 8 + g;
            uint32_t b0 = __float_as_uint(Bs[(k0 + q) * APIT + nn]);
            uint32_t b1 = __float_as_uint(Bs[(k0 + q + 4) * APIT + nn]);
#pragma unroll
            for (int mi = 0; mi < 2; ++mi)
                mma_tf32(acc[mi][nj], a[mi], b0, b1);
        }
    }
}

__global__ __launch_bounds__(512, 1)
void gemm_q_kernel(const float* __restrict__ feat,
                   const float* __restrict__ flow,
                   const float* __restrict__ qw,
                   const float* __restrict__ qb) {
    extern __shared__ float sm[];
    float* Bs = sm + 4 * A_STG_W;                 // resident q_w [128][APIT]
    __shared__ float s_base[2 * MT * 128];        // [half][tile][m]
    __shared__ float s_idt[32];
    uint32_t sm_u = (uint32_t)__cvta_generic_to_shared(sm);
    uint32_t Bs_u = sm_u + (uint32_t)(4 * A_STG_W) * 4u;
    int t  = threadIdx.x;
    int m0_blk = blockIdx.x * (128 * MT);
    int n      = m0_blk / HWSZ;
    int pix0_blk = m0_blk % HWSZ;

    // Group 0: B + A chunk 0
#pragma unroll
    for (int j = 0; j < 8; ++j) {
        int li = j * 512 + t;
        int r = li >> 5, d4 = li & 31;
        cp16(Bs_u + (r * APIT + d4 * 4) * 4, qw + r * DIM + d4 * 4);
    }
    q_fillA(sm_u, feat, n, pix0_blk, 0, t);
    cp_commit();
    q_fillA(sm_u, feat, n, pix0_blk, 1, t); cp_commit();
    q_fillA(sm_u, feat, n, pix0_blk, 2, t); cp_commit();

    // PE base angles for all tiles (overlaps cp.async)
    if (t < 32) s_idt[t] = inv_dt(t);
#pragma unroll
    for (int j = 0; j < 2; ++j) {
        int idx = j * 512 + t;                 // 0..1023
        int half = idx >> 9;
        int tile = (idx >> 7) & 3;
        int m    = idx & 127;
        int pix  = pix0_blk + tile * 128 + m;
        int yy = pix / WW, xx = pix % WW;
        const float* fl = flow + (size_t)((n * HH + yy) * WW + xx) * 2;
        float fx = fl[0], fy = fl[1];
        float full = half ? ((float)xx + fx) : ((float)yy + fy);
        float dec  = full - floorf(full);
        s_base[(half * MT + tile) * 128 + m] = dec * (6.283185307179586f / 2.000001f);
    }

    int w = t >> 5, lane = t & 31;
    int m0w = (w & 3) * 32, n0w = (w >> 2) * 32;
    int q = lane & 3, g = lane >> 2;

    float acc[2][4][4];
#pragma unroll
    for (int mi = 0; mi < 2; ++mi)
#pragma unroll
        for (int nj = 0; nj < 4; ++nj)
#pragma unroll
            for (int e = 0; e < 4; ++e) acc[mi][nj][e] = 0.f;

    const float sc = 0.25f;

#pragma unroll 1
    for (int gc = 0; gc < NCH; ++gc) {
        if (gc <= NCH - 3)      cp_wait<2>();
        else if (gc == NCH - 2) cp_wait<1>();
        else                    cp_wait<0>();
        __syncthreads();
        if (gc + 3 < NCH) { q_fillA(sm_u, feat, n, pix0_blk, gc + 3, t); cp_commit(); }

        float* As = sm + (gc & 3) * A_STG_W;
        int tile = gc >> 2, kb = (gc & 3) * 32;
        // PE for this chunk's channel rows
#pragma unroll
        for (int j = 0; j < 4; ++j) {
            int li = j * 512 + t;
            int pi = li >> 7, m = li & 127;
            int c0 = kb + pi * 2;
            int half = (c0 >> 6) & 1;
            int t2 = (c0 & 63) >> 1;
            float arg = s_base[(half * MT + tile) * 128 + m] * s_idt[t2];
            float s, c;
            sincosf(arg, &s, &c);
            As[(pi * 2) * APIT + m]     += s;
            As[(pi * 2 + 1) * APIT + m] += c;
        }
        __syncthreads();
        // FIX (R7 bug): offset resident B panel to this chunk's channel rows
        mma_chunk_q(As, Bs + kb * APIT, acc, m0w, n0w, q, g);

        if ((gc & 3) == 3) {
            int m0 = m0_blk + tile * 128;
#pragma unroll
            for (int mi = 0; mi < 2; ++mi) {
#pragma unroll
                for (int nj = 0; nj < 4; ++nj) {
                    int r0 = m0 + m0w + mi * 16 + g;
                    int cb = n0w + nj * 8 + q * 2;
                    float b0 = qb[cb], b1 = qb[cb + 1];
                    *(__half2*)(g_Q + (size_t)r0 * DIM + cb) =
                        __floats2half2_rn((acc[mi][nj][0] + b0) * sc,
                                          (acc[mi][nj][1] + b1) * sc);
                    *(__half2*)(g_Q + (size_t)(r0 + 8) * DIM + cb) =
                        __floats2half2_rn((acc[mi][nj][2] + b0) * sc,
                                          (acc[mi][nj][3] + b1) * sc);
                    acc[mi][nj][0] = 0.f; acc[mi][nj][1] = 0.f;
                    acc[mi][nj][2] = 0.f; acc[mi][nj][3] = 0.f;
                }
            }
        }
    }
}

// ---------------------------------------------------------------------------
// Kernel 3: per-pixel attention; fp16 gathers, fp32 math (R6 proven)
// ---------------------------------------------------------------------------
__global__ void attn_kernel(const float* __restrict__ flow, float* __restrict__ out) {
    __shared__ float s_out[8][132];
    __shared__ float s_kb[NWP * DIM];
    __shared__ float s_vb[NWP * DIM];
    int t = threadIdx.x;
    for (int i = t; i < NWP * DIM; i += 256) {
        s_kb[i] = g_kb[i];
        s_vb[i] = g_vb[i];
    }
    __syncthreads();

    int warp = t >> 5, lane = t & 31;
    int p   = blockIdx.x * 8 + warp;
    int n   = p / HWSZ;
    int pix = p % HWSZ;
    int y = pix / WW, x = pix % WW;

    const float* fl = flow + (size_t)((n * HH + y) * WW + x) * 2;
    float fx = fl[0], fy = fl[1];
    int giy = (int)floorf((float)y + fy);
    int gix = (int)floorf((float)x + fx);

    int c0 = lane * 4;
    uint2 qraw = *(const uint2*)(g_Q + (size_t)p * DIM + c0);
    float2 qa = __half22float2(*(__half2*)&qraw.x);
    float2 qc = __half22float2(*(__half2*)&qraw.y);

    int nb[4];
#pragma unroll
    for (int w2 = 0; w2 < 4; ++w2) {
        int hy = giy + (w2 >> 1);
        int wx = gix + (w2 & 1);
        hy = hy < 0 ? 0 : (hy > HH - 1 ? HH - 1 : hy);
        wx = wx < 0 ? 0 : (wx > WW - 1 ? WW - 1 : wx);
        nb[w2] = n * HWSZ + hy * WW + wx;
    }
    uint2 kraw[4], vraw[4];
#pragma unroll
    for (int w2 = 0; w2 < 4; ++w2) {
        kraw[w2] = *(const uint2*)(g_K + (size_t)nb[w2] * DIM + c0);
        vraw[w2] = *(const uint2*)(g_V + (size_t)nb[w2] * DIM + c0);
    }

    float lg[4];
#pragma unroll
    for (int w2 = 0; w2 < 4; ++w2) {
        float2 k01 = __half22float2(*(__half2*)&kraw[w2].x);
        float2 k23 = __half22float2(*(__half2*)&kraw[w2].y);
        const float* kbp = s_kb + w2 * DIM + c0;
        float part = qa.x * (k01.x + kbp[0]) + qa.y * (k01.y + kbp[1]) +
                     qc.x * (k23.x + kbp[2]) + qc.y * (k23.y + kbp[3]);
        part += __shfl_xor_sync(0xffffffffu, part, 1);
        part += __shfl_xor_sync(0xffffffffu, part, 2);
        lg[w2] = part;
    }
    float mx = fmaxf(fmaxf(lg[0], lg[1]), fmaxf(lg[2], lg[3]));
    float e0 = __expf(lg[0] - mx), e1 = __expf(lg[1] - mx);
    float e2 = __expf(lg[2] - mx), e3 = __expf(lg[3] - mx);
    float inv = 1.f / (e0 + e1 + e2 + e3);
    float aw[4] = {e0 * inv, e1 * inv, e2 * inv, e3 * inv};

    float4 o = make_float4(0.f, 0.f, 0.f, 0.f);
#pragma unroll
    for (int w2 = 0; w2 < 4; ++w2) {
        float2 v01 = __half22float2(*(__half2*)&vraw[w2].x);
        float2 v23 = __half22float2(*(__half2*)&vraw[w2].y);
        const float* vbp = s_vb + w2 * DIM + c0;
        float a = aw[w2];
        o.x += a * (v01.x + vbp[0]);
        o.y += a * (v01.y + vbp[1]);
        o.z += a * (v23.x + vbp[2]);
        o.w += a * (v23.y + vbp[3]);
    }
    s_out[warp][c0 + 0] = o.x;
    s_out[warp][c0 + 1] = o.y;
    s_out[warp][c0 + 2] = o.z;
    s_out[warp][c0 + 3] = o.w;
    __syncthreads();

    int p0   = blockIdx.x * 8;
    int n0   = p0 / HWSZ;
    int pix0 = p0 % HWSZ;
    int y0 = pix0 / WW, x0 = pix0 % WW;
#pragma unroll
    for (int rep = 0; rep < 4; ++rep) {
        int d  = (t >> 3) + rep * 32;
        int px = t & 7;
        out[((size_t)(n0 * DIM + d) * HH + y0) * WW + x0 + px] = s_out[px][d];
    }
}

// ---------------------------------------------------------------------------
extern "C" void kernel_launch(void* const* d_in, const int* in_sizes, int n_in,
                              void* d_out, int out_size) {
    const float* feat_supp = (const float*)d_in[0];
    const float* feat_curr = (const float*)d_in[1];
    const float* flow      = (const float*)d_in[2];
    const float* q_w       = (const float*)d_in[3];
    const float* q_b       = (const float*)d_in[4];
    const float* k_w       = (const float*)d_in[5];
    const float* k_b       = (const float*)d_in[6];
    const float* v_w       = (const float*)d_in[7];
    const float* v_b       = (const float*)d_in[8];
    float* out = (float*)d_out;

    const int smem_kv = (4 * A_STG_W + 128 * BPIT) * (int)sizeof(float);  // 204800 B
    const int smem_q  = (4 * A_STG_W + 128 * APIT) * (int)sizeof(float);  // 139264 B
    cudaFuncSetAttribute(gemm_kv_kernel, cudaFuncAttributeMaxDynamicSharedMemorySize, smem_kv);
    cudaFuncSetAttribute(gemm_q_kernel,  cudaFuncAttributeMaxDynamicSharedMemorySize, smem_q);

    gemm_kv_kernel<<<NHW / (128 * MT) + KV_BIAS_BLOCKS, 512, smem_kv>>>(
        feat_supp, k_w, v_w, k_b, v_b);
    gemm_q_kernel<<<NHW / (128 * MT), 512, smem_q>>>(feat_curr, flow, q_w, q_b);
    attn_kernel<<<NHW / 8, 256>>>(flow, out);
}